// round 6
// baseline (speedup 1.0000x reference)
#include <cuda_runtime.h>

#define DD 64
#define NMAX 100352
#define EMAX 1703936
#define ALPHA 0.2f

// Scratch (static device arrays; no allocation anywhere)
__device__ float2 g_src[NMAX];   // per-node {s_src_h0, s_src_h1}
__device__ float2 g_dst[NMAX];   // per-node {s_dst_h0, s_dst_h1}
__device__ float2 g_rs[NMAX];    // per-node rowsums {r0, r1}
__device__ float2 g_ev[EMAX];    // per-edge {e_h0, e_h1}

// Fused: zero out[] + g_rs[], and per-node dual-head src/dst dot products.
// Grid covers nvec4 = n*16 float4 slots of out; node work done for i < n.
__global__ void k_prep(const float* __restrict__ x, const float* __restrict__ W,
                       const float* __restrict__ a, float* __restrict__ out,
                       int n, int nvec4) {
    __shared__ float2 cs[DD];  // {W0[k]*a0[k],    W1[k]*a1[k]}
    __shared__ float2 cd[DD];  // {W0[k]*a0[D+k],  W1[k]*a1[D+k]}
    for (int k = threadIdx.x; k < DD; k += blockDim.x) {
        float w0 = W[k], w1 = W[DD + k];
        cs[k] = make_float2(w0 * a[k],      w1 * a[2 * DD + k]);
        cd[k] = make_float2(w0 * a[DD + k], w1 * a[3 * DD + k]);
    }
    __syncthreads();
    int i = blockIdx.x * blockDim.x + threadIdx.x;

    // zero one float4 of out per thread
    if (i < nvec4) ((float4*)out)[i] = make_float4(0.f, 0.f, 0.f, 0.f);

    if (i < n) {
        g_rs[i] = make_float2(0.f, 0.f);
        const float4* xv = (const float4*)(x + (size_t)i * DD);
        float s0 = 0.f, s1 = 0.f, d0 = 0.f, d1 = 0.f;
#pragma unroll
        for (int k4 = 0; k4 < DD / 4; k4++) {
            float4 v = xv[k4];
            float vv[4] = {v.x, v.y, v.z, v.w};
#pragma unroll
            for (int j = 0; j < 4; j++) {
                float2 c1 = cs[4 * k4 + j];
                float2 c2 = cd[4 * k4 + j];
                s0 += vv[j] * c1.x; s1 += vv[j] * c1.y;
                d0 += vv[j] * c2.x; d1 += vv[j] * c2.y;
            }
        }
        g_src[i] = make_float2(s0, s1);
        g_dst[i] = make_float2(d0, d1);
    }
}

// Edge pass 1: attention coefficients + rowsum reduction (vector RED, no return).
__global__ void k_edge1(const int* __restrict__ ei, int E) {
    int e = blockIdx.x * blockDim.x + threadIdx.x;
    if (e >= E) return;
    int r = __ldg(ei + e);
    int c = __ldg(ei + E + e);
    float2 ss = __ldg(&g_src[r]);   // written by k_prep (prior kernel) — safe
    float2 sd = __ldg(&g_dst[c]);
    float sc0 = ss.x + sd.x;
    float sc1 = ss.y + sd.y;
    sc0 = sc0 > 0.f ? sc0 : ALPHA * sc0;
    sc1 = sc1 > 0.f ? sc1 : ALPHA * sc1;
    float e0 = __expf(sc0);
    float e1 = __expf(sc1);
    g_ev[e] = make_float2(e0, e1);
    asm volatile("red.global.add.v2.f32 [%0], {%1,%2};"
                 :: "l"(&g_rs[r]), "f"(e0), "f"(e1) : "memory");
}

// Edge pass 2: SpMM with a single scalar weight per edge. 16 lanes per edge,
// each lane handles one float4 (64 features) via red.global.add.v4.f32.
// ALL scalar loads live in the lane-0 leader: it loads r, c, e-values, rowsums,
// computes w = 0.5*(e0/r0 + e1/r1) (normalization + head-mean folded in; MUFU
// divides hidden under memory latency), then broadcasts r, c, w via width-16
// shuffles. Non-leader lanes issue exactly one LDG (the float4 gather) — cuts
// LSU issue pressure ~3x in the hot kernel. No early return before shuffles:
// tail lanes clamp the edge index and predicate the load/RED so full-mask
// __shfl_sync is always executed by all 32 lanes.
__global__ void k_spmm(const int* __restrict__ ei, const float* __restrict__ x,
                       float* __restrict__ out, int E) {
    int gid = blockIdx.x * blockDim.x + threadIdx.x;
    int e = gid >> 4;
    bool valid = (e < E);
    int ec = valid ? e : (E - 1);      // clamped, safe to read
    int l = gid & 15;
    int r = 0, c = 0;
    float w = 0.f;
    if (l == 0) {
        r = __ldg(ei + ec);
        c = __ldg(ei + E + ec);
        float2 ev = __ldg(&g_ev[ec]);  // written by k_edge1 (prior kernel)
        float2 rs = __ldg(&g_rs[r]);
        w = 0.5f * (__fdividef(ev.x, rs.x) + __fdividef(ev.y, rs.y));
    }
    // broadcast from lane 0 of each 16-wide segment
    r = __shfl_sync(0xffffffffu, r, 0, 16);
    c = __shfl_sync(0xffffffffu, c, 0, 16);
    w = __shfl_sync(0xffffffffu, w, 0, 16);
    if (valid) {
        float4 v = __ldg((const float4*)x + (size_t)c * 16 + l);
        float* dst = out + (size_t)r * 64 + l * 4;
        asm volatile("red.global.add.v4.f32 [%0], {%1,%2,%3,%4};"
                     :: "l"(dst), "f"(w * v.x), "f"(w * v.y), "f"(w * v.z), "f"(w * v.w)
                     : "memory");
    }
}

extern "C" void kernel_launch(void* const* d_in, const int* in_sizes, int n_in,
                              void* d_out, int out_size) {
    const float* x  = (const float*)d_in[0];   // [N, 64]
    const int*   ei = (const int*)d_in[1];     // [2, E]
    const float* W  = (const float*)d_in[2];   // [2, 64]
    const float* a  = (const float*)d_in[3];   // [2, 128]
    float* out = (float*)d_out;                // [N, 64]

    int n = in_sizes[0] / DD;
    int E = in_sizes[1] / 2;
    if (n > NMAX) n = NMAX;
    if (E > EMAX) E = EMAX;

    int nvec4 = out_size / 4;
    int prep_t = nvec4 > n ? nvec4 : n;
    k_prep<<<(prep_t + 255) / 256, 256>>>(x, W, a, out, n, nvec4);
    k_edge1<<<(E + 255) / 256, 256>>>(ei, E);
    long long t = (long long)E * 16;
    k_spmm<<<(int)((t + 255) / 256), 256>>>(ei, x, out, E);
}